// round 5
// baseline (speedup 1.0000x reference)
#include <cuda_runtime.h>
#include <cuda_bf16.h>
#include <cstdint>

#define N_NODES 100000
#define N_EDGES 600000
#define DIM 128
#define KTOT 640   // 512 (4 bases x 128) + 128 (root)
#define MTILE 64

// ---------------- scratch (static device globals; no runtime alloc) ----------------
__device__ float g_h0[(size_t)N_NODES * DIM];
__device__ float g_h1[(size_t)N_NODES * DIM];
__device__ float4 g_coeff1[N_EDGES];          // CSR-ordered, layer 1
__device__ float4 g_coeff2[N_EDGES];          // CSR-ordered, layer 2
__device__ int   g_csr_src[N_EDGES];
__device__ int   g_deg[N_NODES];
__device__ int   g_rowptr[N_NODES + 1];
__device__ int   g_cursor[N_NODES];
__device__ float g_invdeg[N_NODES];
__device__ int   g_bsum[128];
__device__ int   g_boff[129];
__device__ __nv_bfloat16 g_Whi[128 * KTOT];   // [n][k]
__device__ __nv_bfloat16 g_Wlo[128 * KTOT];   // [n][k]

// ---------------- helpers ----------------
__device__ __forceinline__ uint32_t smem_u32(const void* p) {
    uint32_t a;
    asm("{ .reg .u64 t; cvta.to.shared.u64 t, %1; cvt.u32.u64 %0, t; }" : "=r"(a) : "l"(p));
    return a;
}
__device__ __forceinline__ void ldm_x4(uint32_t* r, uint32_t addr) {
    asm volatile("ldmatrix.sync.aligned.m8n8.x4.shared.b16 {%0,%1,%2,%3}, [%4];"
                 : "=r"(r[0]), "=r"(r[1]), "=r"(r[2]), "=r"(r[3]) : "r"(addr));
}
__device__ __forceinline__ void mma16816(float* c, const uint32_t* a, const uint32_t* b) {
    asm volatile("mma.sync.aligned.m16n8k16.row.col.f32.bf16.bf16.f32 "
                 "{%0,%1,%2,%3}, {%4,%5,%6,%7}, {%8,%9}, {%0,%1,%2,%3};"
                 : "+f"(c[0]), "+f"(c[1]), "+f"(c[2]), "+f"(c[3])
                 : "r"(a[0]), "r"(a[1]), "r"(a[2]), "r"(a[3]), "r"(b[0]), "r"(b[1]));
}
__device__ __forceinline__ void cp16(uint32_t dst, const void* src) {
    asm volatile("cp.async.cg.shared.global [%0], [%1], 16;" :: "r"(dst), "l"(src));
}
#define CP_COMMIT() asm volatile("cp.async.commit_group;" ::: "memory")
#define CP_WAIT(N)  asm volatile("cp.async.wait_group %0;" :: "n"(N) : "memory")

__device__ __forceinline__ uint32_t pack_hi(float a, float b) {
    __nv_bfloat16 ha = __float2bfloat16(a), hb = __float2bfloat16(b);
    return (uint32_t)__bfloat16_as_ushort(ha) | ((uint32_t)__bfloat16_as_ushort(hb) << 16);
}
__device__ __forceinline__ uint32_t pack_lo(float a, float b) {
    __nv_bfloat16 ha = __float2bfloat16(a), hb = __float2bfloat16(b);
    __nv_bfloat16 la = __float2bfloat16(a - __bfloat162float(ha));
    __nv_bfloat16 lb = __float2bfloat16(b - __bfloat162float(hb));
    return (uint32_t)__bfloat16_as_ushort(la) | ((uint32_t)__bfloat16_as_ushort(lb) << 16);
}

// ---------------- CSR build ----------------
__global__ void k_zero_deg() {
    int i = blockIdx.x * blockDim.x + threadIdx.x;
    if (i < N_NODES) g_deg[i] = 0;
}
__global__ void k_hist(const int* __restrict__ dst) {
    int e = blockIdx.x * blockDim.x + threadIdx.x;
    if (e < N_EDGES) atomicAdd(&g_deg[dst[e]], 1);
}
__global__ void k_scan1() {
    __shared__ int sh[1024];
    int b = blockIdx.x, t = threadIdx.x;
    int i = b * 1024 + t;
    int v = (i < N_NODES) ? g_deg[i] : 0;
    sh[t] = v;
    __syncthreads();
    #pragma unroll
    for (int off = 1; off < 1024; off <<= 1) {
        int x = (t >= off) ? sh[t - off] : 0;
        __syncthreads();
        sh[t] += x;
        __syncthreads();
    }
    if (i < N_NODES) g_rowptr[i] = sh[t] - v;
    if (t == 1023) g_bsum[b] = sh[1023];
}
__global__ void k_scan2(int nblocks) {
    __shared__ int sh[128];
    int t = threadIdx.x;
    int v = (t < nblocks) ? g_bsum[t] : 0;
    sh[t] = v;
    __syncthreads();
    #pragma unroll
    for (int off = 1; off < 128; off <<= 1) {
        int x = (t >= off) ? sh[t - off] : 0;
        __syncthreads();
        sh[t] += x;
        __syncthreads();
    }
    g_boff[t] = sh[t] - v;
    if (t == nblocks - 1) g_boff[128] = sh[t];
}
__global__ void k_scan3() {
    int b = blockIdx.x, t = threadIdx.x;
    int i = b * 1024 + t;
    if (i < N_NODES) {
        int rp = g_rowptr[i] + g_boff[b];
        g_rowptr[i] = rp;
        g_cursor[i] = rp;
        g_invdeg[i] = 1.0f / fmaxf((float)g_deg[i], 1.0f);
    }
    if (b == 0 && t == 0) g_rowptr[N_NODES] = g_boff[128];
}
// scatter + per-edge coefficients for BOTH layers (kills eid indirection)
__global__ void k_scatter(const int* __restrict__ dst, const int* __restrict__ src,
                          const int* __restrict__ etype, const float* __restrict__ enorm,
                          const float4* __restrict__ att1, const float4* __restrict__ att2) {
    int e = blockIdx.x * blockDim.x + threadIdx.x;
    if (e >= N_EDGES) return;
    int pos = atomicAdd(&g_cursor[dst[e]], 1);
    g_csr_src[pos] = src[e];
    int t = etype[e];
    float n = enorm[e];
    float4 a1 = att1[t];
    float4 a2 = att2[t];
    g_coeff1[pos] = make_float4(a1.x * n, a1.y * n, a1.z * n, a1.w * n);
    g_coeff2[pos] = make_float4(a2.x * n, a2.y * n, a2.z * n, a2.w * n);
}

// ---------------- embedding gather ----------------
__global__ void k_gather(const int* __restrict__ entity, const float4* __restrict__ tbl) {
    int t = blockIdx.x * blockDim.x + threadIdx.x;
    if (t >= N_NODES * 32) return;
    int node = t >> 5;
    int lane = t & 31;
    int ent = entity[node];
    ((float4*)g_h0)[(size_t)node * 32 + lane] = tbl[(size_t)ent * 32 + lane];
}

// ---------------- weight split: W[k][n] -> Whi/Wlo [n][k] bf16 ----------------
__global__ void k_prepw(const float* __restrict__ basis, const float* __restrict__ root) {
    int idx = blockIdx.x * blockDim.x + threadIdx.x;
    if (idx >= 128 * KTOT) return;
    int n = idx / KTOT;
    int k = idx % KTOT;
    float w = (k < 512) ? basis[(size_t)k * 128 + n] : root[(size_t)(k - 512) * 128 + n];
    __nv_bfloat16 hi = __float2bfloat16(w);
    __nv_bfloat16 lo = __float2bfloat16(w - __bfloat162float(hi));
    g_Whi[n * KTOT + k] = hi;
    g_Wlo[n * KTOT + k] = lo;
}

// ---------------- fused aggregation + GEMM ----------------
// CTA = 64 nodes. Phase 1: aggregate into smem A tile [64 x 640] bf16 hi/lo
// (row stride 1296B -> conflict-free ldmatrix). Phase 2: 3-pass hi/lo HMMA
// against cp.async double-buffered weight tiles (BK=32).
#define A_STRB 1296                        // A smem row stride bytes (648 bf16)
#define A_HI_OFF 0
#define A_LO_OFF (MTILE * A_STRB)          // 82944
#define B_OFF    (2 * MTILE * A_STRB)      // 165888
#define B_TILE   10240                     // 128 rows x 40 bf16 (80B stride)
#define B_BUF    (2 * B_TILE)              // hi + lo
#define SMEM_FUSED (B_OFF + 2 * B_BUF)     // 206848

__global__ __launch_bounds__(256) void k_fused(
    int layer, const float* __restrict__ bias, float* __restrict__ out_param, int do_relu)
{
    extern __shared__ char smem[];
    uint32_t sbase = smem_u32(smem);
    const float4* X4 = (const float4*)((layer == 0) ? g_h0 : g_h1);
    const float4* cf = (layer == 0) ? g_coeff1 : g_coeff2;
    float* out = (layer == 0) ? g_h1 : out_param;

    int tid = threadIdx.x;
    int wid = tid >> 5;
    int lane = tid & 31;
    int bm = blockIdx.x * MTILE;

    // ---- B prefetch: chunks 0,1 (each thread loads 2 16B chunks per tile) ----
    int lr = tid >> 1;
    int lc0 = (tid & 1) * 2;
    auto load_B = [&](int ch, int buf) {
        int kc = ch * 32;
        uint32_t bo = sbase + B_OFF + buf * B_BUF;
        #pragma unroll
        for (int c = 0; c < 2; c++) {
            int cc = lc0 + c;
            uint32_t dof = (uint32_t)lr * 80 + cc * 16;
            int eof = kc + cc * 8;
            cp16(bo + dof,          g_Whi + lr * KTOT + eof);
            cp16(bo + B_TILE + dof, g_Wlo + lr * KTOT + eof);
        }
    };
    load_B(0, 0); CP_COMMIT();
    load_B(1, 1); CP_COMMIT();

    // ---- Phase 1: aggregate 8 nodes per warp into smem A ----
    #pragma unroll 1
    for (int i = 0; i < 8; i++) {
        int row = wid * 8 + i;
        int node = bm + row;
        float4 s0 = make_float4(0.f, 0.f, 0.f, 0.f);
        float4 s1 = s0, s2 = s0, s3 = s0, xs = s0;
        if (node < N_NODES) {
            int beg = g_rowptr[node], end = g_rowptr[node + 1];
            int p = beg;
            #pragma unroll 1
            for (; p + 4 <= end; p += 4) {
                float4 c0 = cf[p], c1 = cf[p + 1], c2 = cf[p + 2], c3 = cf[p + 3];
                int i0 = g_csr_src[p], i1 = g_csr_src[p + 1];
                int i2 = g_csr_src[p + 2], i3 = g_csr_src[p + 3];
                float4 x0 = X4[(size_t)i0 * 32 + lane];
                float4 x1 = X4[(size_t)i1 * 32 + lane];
                float4 x2 = X4[(size_t)i2 * 32 + lane];
                float4 x3 = X4[(size_t)i3 * 32 + lane];
                s0.x = fmaf(c0.x, x0.x, s0.x); s0.y = fmaf(c0.x, x0.y, s0.y);
                s0.z = fmaf(c0.x, x0.z, s0.z); s0.w = fmaf(c0.x, x0.w, s0.w);
                s1.x = fmaf(c0.y, x0.x, s1.x); s1.y = fmaf(c0.y, x0.y, s1.y);
                s1.z = fmaf(c0.y, x0.z, s1.z); s1.w = fmaf(c0.y, x0.w, s1.w);
                s2.x = fmaf(c0.z, x0.x, s2.x); s2.y = fmaf(c0.z, x0.y, s2.y);
                s2.z = fmaf(c0.z, x0.z, s2.z); s2.w = fmaf(c0.z, x0.w, s2.w);
                s3.x = fmaf(c0.w, x0.x, s3.x); s3.y = fmaf(c0.w, x0.y, s3.y);
                s3.z = fmaf(c0.w, x0.z, s3.z); s3.w = fmaf(c0.w, x0.w, s3.w);
                s0.x = fmaf(c1.x, x1.x, s0.x); s0.y = fmaf(c1.x, x1.y, s0.y);
                s0.z = fmaf(c1.x, x1.z, s0.z); s0.w = fmaf(c1.x, x1.w, s0.w);
                s1.x = fmaf(c1.y, x1.x, s1.x); s1.y = fmaf(c1.y, x1.y, s1.y);
                s1.z = fmaf(c1.y, x1.z, s1.z); s1.w = fmaf(c1.y, x1.w, s1.w);
                s2.x = fmaf(c1.z, x1.x, s2.x); s2.y = fmaf(c1.z, x1.y, s2.y);
                s2.z = fmaf(c1.z, x1.z, s2.z); s2.w = fmaf(c1.z, x1.w, s2.w);
                s3.x = fmaf(c1.w, x1.x, s3.x); s3.y = fmaf(c1.w, x1.y, s3.y);
                s3.z = fmaf(c1.w, x1.z, s3.z); s3.w = fmaf(c1.w, x1.w, s3.w);
                s0.x = fmaf(c2.x, x2.x, s0.x); s0.y = fmaf(c2.x, x2.y, s0.y);
                s0.z = fmaf(c2.x, x2.z, s0.z); s0.w = fmaf(c2.x, x2.w, s0.w);
                s1.x = fmaf(c2.y, x2.x, s1.x); s1.y = fmaf(c2.y, x2.y, s1.y);
                s1.z = fmaf(c2.y, x2.z, s1.z); s1.w = fmaf(c2.y, x2.w, s1.w);
                s2.x = fmaf(c2.z, x2.x, s2.x); s2.y = fmaf(c2.z, x2.y, s2.y);
                s2.z = fmaf(c2.z, x2.z, s2.z); s2.w = fmaf(c2.z, x2.w, s2.w);
                s3.x = fmaf(c2.w, x2.x, s3.x); s3.y = fmaf(c2.w, x2.y, s3.y);
                s3.z = fmaf(c2.w, x2.z, s3.z); s3.w = fmaf(c2.w, x2.w, s3.w);
                s0.x = fmaf(c3.x, x3.x, s0.x); s0.y = fmaf(c3.x, x3.y, s0.y);
                s0.z = fmaf(c3.x, x3.z, s0.z); s0.w = fmaf(c3.x, x3.w, s0.w);
                s1.x = fmaf(c3.y, x3.x, s1.x); s1.y = fmaf(c3.y, x3.y, s1.y);
                s1.z = fmaf(c3.y, x3.z, s1.z); s1.w = fmaf(c3.y, x3.w, s1.w);
                s2.x = fmaf(c3.z, x3.x, s2.x); s2.y = fmaf(c3.z, x3.y, s2.y);
                s2.z = fmaf(c3.z, x3.z, s2.z); s2.w = fmaf(c3.z, x3.w, s2.w);
                s3.x = fmaf(c3.w, x3.x, s3.x); s3.y = fmaf(c3.w, x3.y, s3.y);
                s3.z = fmaf(c3.w, x3.z, s3.z); s3.w = fmaf(c3.w, x3.w, s3.w);
            }
            #pragma unroll 1
            for (; p < end; ++p) {
                float4 c = cf[p];
                int sn = g_csr_src[p];
                float4 xv = X4[(size_t)sn * 32 + lane];
                s0.x = fmaf(c.x, xv.x, s0.x); s0.y = fmaf(c.x, xv.y, s0.y);
                s0.z = fmaf(c.x, xv.z, s0.z); s0.w = fmaf(c.x, xv.w, s0.w);
                s1.x = fmaf(c.y, xv.x, s1.x); s1.y = fmaf(c.y, xv.y, s1.y);
                s1.z = fmaf(c.y, xv.z, s1.z); s1.w = fmaf(c.y, xv.w, s1.w);
                s2.x = fmaf(c.z, xv.x, s2.x); s2.y = fmaf(c.z, xv.y, s2.y);
                s2.z = fmaf(c.z, xv.z, s2.z); s2.w = fmaf(c.z, xv.w, s2.w);
                s3.x = fmaf(c.w, xv.x, s3.x); s3.y = fmaf(c.w, xv.y, s3.y);
                s3.z = fmaf(c.w, xv.z, s3.z); s3.w = fmaf(c.w, xv.w, s3.w);
            }
            float d = g_invdeg[node];
            s0.x *= d; s0.y *= d; s0.z *= d; s0.w *= d;
            s1.x *= d; s1.y *= d; s1.z *= d; s1.w *= d;
            s2.x *= d; s2.y *= d; s2.z *= d; s2.w *= d;
            s3.x *= d; s3.y *= d; s3.z *= d; s3.w *= d;
            xs = X4[(size_t)node * 32 + lane];
        }
        // write A row to smem: basis b -> cols b*128 + 4*lane; root -> 512 + 4*lane
        char* hrow = smem + A_HI_OFF + row * A_STRB;
        char* lrow = smem + A_LO_OFF + row * A_STRB;
        uint32_t co = 8 * lane;
        *(uint2*)(hrow + co)        = make_uint2(pack_hi(s0.x, s0.y), pack_hi(s0.z, s0.w));
        *(uint2*)(lrow + co)        = make_uint2(pack_lo(s0.x, s0.y), pack_lo(s0.z, s0.w));
        *(uint2*)(hrow + 256 + co)  = make_uint2(pack_hi(s1.x, s1.y), pack_hi(s1.z, s1.w));
        *(uint2*)(lrow + 256 + co)  = make_uint2(pack_lo(s1.x, s1.y), pack_lo(s1.z, s1.w));
        *(uint2*)(hrow + 512 + co)  = make_uint2(pack_hi(s2.x, s2.y), pack_hi(s2.z, s2.w));
        *(uint2*)(lrow + 512 + co)  = make_uint2(pack_lo(s2.x, s2.y), pack_lo(s2.z, s2.w));
        *(uint2*)(hrow + 768 + co)  = make_uint2(pack_hi(s3.x, s3.y), pack_hi(s3.z, s3.w));
        *(uint2*)(lrow + 768 + co)  = make_uint2(pack_lo(s3.x, s3.y), pack_lo(s3.z, s3.w));
        *(uint2*)(hrow + 1024 + co) = make_uint2(pack_hi(xs.x, xs.y), pack_hi(xs.z, xs.w));
        *(uint2*)(lrow + 1024 + co) = make_uint2(pack_lo(xs.x, xs.y), pack_lo(xs.z, xs.w));
    }
    __syncthreads();

    // ---- Phase 2: GEMM 64x128 over K=640 ----
    int wm0 = (wid >> 2) * 32;   // 2 warp rows of 32
    int wn0 = (wid & 3) * 32;    // 4 warp cols of 32

    float acc[2][4][4];
    #pragma unroll
    for (int i = 0; i < 2; i++)
        #pragma unroll
        for (int j = 0; j < 4; j++)
            #pragma unroll
            for (int q = 0; q < 4; q++) acc[i][j][q] = 0.f;

    uint32_t a_off = (uint32_t)(lane & 15) * A_STRB + (uint32_t)(lane >> 4) * 16;
    int bg = lane >> 3;
    uint32_t b_off = (uint32_t)((bg >> 1) * 8 + (lane & 7)) * 80 + (uint32_t)(bg & 1) * 16;

    #pragma unroll 1
    for (int ch = 0; ch < 20; ch++) {
        int buf = ch & 1;
        if (ch == 19) { CP_WAIT(0); } else { CP_WAIT(1); }
        __syncthreads();

        uint32_t b_hi_base = sbase + B_OFF + buf * B_BUF;
        uint32_t b_lo_base = b_hi_base + B_TILE;
        uint32_t a_kbyte = (uint32_t)ch * 64;

        #pragma unroll
        for (int kk = 0; kk < 2; kk++) {
            uint32_t kb = a_kbyte + (uint32_t)kk * 32;
            uint32_t ahi[2][4], alo[2][4];
            #pragma unroll
            for (int mf = 0; mf < 2; mf++) {
                uint32_t o = (uint32_t)(wm0 + mf * 16) * A_STRB + a_off + kb;
                ldm_x4(ahi[mf], sbase + A_HI_OFF + o);
                ldm_x4(alo[mf], sbase + A_LO_OFF + o);
            }
            uint32_t kbb = (uint32_t)kk * 32;
            uint32_t bhi[4][2], blo[4][2];
            #pragma unroll
            for (int pr = 0; pr < 2; pr++) {
                uint32_t o = (uint32_t)(wn0 + pr * 16) * 80 + b_off + kbb;
                uint32_t th[4], tl[4];
                ldm_x4(th, b_hi_base + o);
                ldm_x4(tl, b_lo_base + o);
                bhi[pr * 2][0] = th[0]; bhi[pr * 2][1] = th[1];
                bhi[pr * 2 + 1][0] = th[2]; bhi[pr * 2 + 1][1] = th[3];
                blo[pr * 2][0] = tl[0]; blo[pr * 2][1] = tl[1];
                blo[pr * 2 + 1][0] = tl[2]; blo[pr * 2 + 1][1] = tl[3];
            }
            #pragma unroll
            for (int mf = 0; mf < 2; mf++)
                #pragma unroll
                for (int nf = 0; nf < 4; nf++) {
                    mma16816(acc[mf][nf], ahi[mf], bhi[nf]);
                    mma16816(acc[mf][nf], ahi[mf], blo[nf]);
                    mma16816(acc[mf][nf], alo[mf], bhi[nf]);
                }
        }
        __syncthreads();
        if (ch + 2 < 20) { load_B(ch + 2, buf); CP_COMMIT(); }
    }

    // ---- epilogue ----
    int qm = lane >> 2;
    int qn = (lane & 3) * 2;
    #pragma unroll
    for (int nf = 0; nf < 4; nf++) {
        int n = wn0 + nf * 8 + qn;
        float b0 = bias[n], b1 = bias[n + 1];
        #pragma unroll
        for (int mf = 0; mf < 2; mf++) {
            int m0 = bm + wm0 + mf * 16 + qm;
            float2 lo = make_float2(acc[mf][nf][0] + b0, acc[mf][nf][1] + b1);
            float2 hi = make_float2(acc[mf][nf][2] + b0, acc[mf][nf][3] + b1);
            if (do_relu) {
                lo.x = fmaxf(lo.x, 0.f); lo.y = fmaxf(lo.y, 0.f);
                hi.x = fmaxf(hi.x, 0.f); hi.y = fmaxf(hi.y, 0.f);
            }
            if (m0 < N_NODES)     *(float2*)(out + (size_t)m0 * 128 + n) = lo;
            if (m0 + 8 < N_NODES) *(float2*)(out + (size_t)(m0 + 8) * 128 + n) = hi;
        }
    }
}

// ---------------- relation_emb passthrough ----------------
__global__ void k_copyrel(const float* __restrict__ rel, float* __restrict__ out) {
    int i = blockIdx.x * blockDim.x + threadIdx.x;
    if (i < 500 * 128) out[i] = rel[i];
}

// ---------------- launch ----------------
extern "C" void kernel_launch(void* const* d_in, const int* in_sizes, int n_in,
                              void* d_out, int out_size) {
    const int*   entity       = (const int*)d_in[0];
    const int*   edge_index   = (const int*)d_in[1];
    const int*   edge_type    = (const int*)d_in[2];
    const float* edge_norm    = (const float*)d_in[3];
    // d_in[4] = DAD_rel (unused by reference output)
    const float* entity_table = (const float*)d_in[5];
    const float* relation_emb = (const float*)d_in[6];
    const float* basis1 = (const float*)d_in[7];
    const float* att1   = (const float*)d_in[8];
    const float* root1  = (const float*)d_in[9];
    const float* bias1  = (const float*)d_in[10];
    const float* basis2 = (const float*)d_in[11];
    const float* att2   = (const float*)d_in[12];
    const float* root2  = (const float*)d_in[13];
    const float* bias2  = (const float*)d_in[14];

    const int* src = edge_index;
    const int* dst = edge_index + N_EDGES;
    float* out = (float*)d_out;

    static int smem_set = 0;
    if (!smem_set) {
        cudaFuncSetAttribute(k_fused, cudaFuncAttributeMaxDynamicSharedMemorySize, SMEM_FUSED);
        smem_set = 1;
    }

    int scan_blocks = (N_NODES + 1023) / 1024;   // 98

    // CSR by dst (+ CSR-ordered coefficients for both layers)
    k_zero_deg<<<(N_NODES + 255) / 256, 256>>>();
    k_hist<<<(N_EDGES + 255) / 256, 256>>>(dst);
    k_scan1<<<scan_blocks, 1024>>>();
    k_scan2<<<1, 128>>>(scan_blocks);
    k_scan3<<<scan_blocks, 1024>>>();
    k_scatter<<<(N_EDGES + 255) / 256, 256>>>(dst, src, edge_type, edge_norm,
                                              (const float4*)att1, (const float4*)att2);

    // h0 = entity_table[entity]
    k_gather<<<(N_NODES * 32 + 255) / 256, 256>>>(entity, (const float4*)entity_table);

    int fused_blocks = (N_NODES + MTILE - 1) / MTILE;   // 1563

    // layer 1 (relu) -> g_h1
    k_prepw<<<(128 * KTOT + 255) / 256, 256>>>(basis1, root1);
    k_fused<<<fused_blocks, 256, SMEM_FUSED>>>(0, bias1, nullptr, 1);

    // layer 2 (no relu) -> d_out
    k_prepw<<<(128 * KTOT + 255) / 256, 256>>>(basis2, root2);
    k_fused<<<fused_blocks, 256, SMEM_FUSED>>>(1, bias2, out, 0);

    // append relation_emb
    k_copyrel<<<(500 * 128 + 255) / 256, 256>>>(relation_emb, out + (size_t)N_NODES * DIM);
}

// round 6
// speedup vs baseline: 1.3459x; 1.3459x over previous
#include <cuda_runtime.h>
#include <cuda_bf16.h>
#include <cstdint>

#define N_NODES 100000
#define N_EDGES 600000
#define DIM 128
#define KTOT 640   // 512 (4 bases x 128) + 128 (root)

// ---------------- scratch (static device globals; no runtime alloc) ----------------
__device__ float g_h0[(size_t)N_NODES * DIM];
__device__ float g_h1[(size_t)N_NODES * DIM];
__device__ __nv_bfloat16 g_A1hi[(size_t)N_NODES * KTOT];  // layer-1 GEMM A = [S1 | h0]
__device__ __nv_bfloat16 g_A1lo[(size_t)N_NODES * KTOT];
__device__ __nv_bfloat16 g_A2hi[(size_t)N_NODES * KTOT];  // layer-2 GEMM A = [S2 | h1]
__device__ __nv_bfloat16 g_A2lo[(size_t)N_NODES * KTOT];
__device__ float4 g_coeff1[N_EDGES];          // CSR-ordered, layer 1
__device__ float4 g_coeff2[N_EDGES];          // CSR-ordered, layer 2
__device__ int   g_csr_src[N_EDGES];
__device__ int   g_deg[N_NODES];
__device__ int   g_rowptr[N_NODES + 1];
__device__ int   g_cursor[N_NODES];
__device__ float g_invdeg[N_NODES];
__device__ int   g_bsum[128];
__device__ int   g_boff[129];
__device__ __nv_bfloat16 g_Whi[128 * KTOT];   // [n][k]
__device__ __nv_bfloat16 g_Wlo[128 * KTOT];   // [n][k]

// ---------------- helpers ----------------
__device__ __forceinline__ uint32_t smem_u32(const void* p) {
    uint32_t a;
    asm("{ .reg .u64 t; cvta.to.shared.u64 t, %1; cvt.u32.u64 %0, t; }" : "=r"(a) : "l"(p));
    return a;
}
__device__ __forceinline__ void ldm_x4(uint32_t* r, uint32_t addr) {
    asm volatile("ldmatrix.sync.aligned.m8n8.x4.shared.b16 {%0,%1,%2,%3}, [%4];"
                 : "=r"(r[0]), "=r"(r[1]), "=r"(r[2]), "=r"(r[3]) : "r"(addr));
}
__device__ __forceinline__ void mma16816(float* c, const uint32_t* a, const uint32_t* b) {
    asm volatile("mma.sync.aligned.m16n8k16.row.col.f32.bf16.bf16.f32 "
                 "{%0,%1,%2,%3}, {%4,%5,%6,%7}, {%8,%9}, {%0,%1,%2,%3};"
                 : "+f"(c[0]), "+f"(c[1]), "+f"(c[2]), "+f"(c[3])
                 : "r"(a[0]), "r"(a[1]), "r"(a[2]), "r"(a[3]), "r"(b[0]), "r"(b[1]));
}
__device__ __forceinline__ void cp16(uint32_t dst, const void* src) {
    asm volatile("cp.async.cg.shared.global [%0], [%1], 16;" :: "r"(dst), "l"(src));
}
#define CP_COMMIT() asm volatile("cp.async.commit_group;" ::: "memory")
#define CP_WAIT(N)  asm volatile("cp.async.wait_group %0;" :: "n"(N) : "memory")

__device__ __forceinline__ uint32_t pack_hi(float a, float b) {
    __nv_bfloat16 ha = __float2bfloat16(a), hb = __float2bfloat16(b);
    return (uint32_t)__bfloat16_as_ushort(ha) | ((uint32_t)__bfloat16_as_ushort(hb) << 16);
}
__device__ __forceinline__ uint32_t pack_lo(float a, float b) {
    __nv_bfloat16 ha = __float2bfloat16(a), hb = __float2bfloat16(b);
    __nv_bfloat16 la = __float2bfloat16(a - __bfloat162float(ha));
    __nv_bfloat16 lb = __float2bfloat16(b - __bfloat162float(hb));
    return (uint32_t)__bfloat16_as_ushort(la) | ((uint32_t)__bfloat16_as_ushort(lb) << 16);
}

// ---------------- CSR build ----------------
__global__ void k_zero_deg() {
    int i = blockIdx.x * blockDim.x + threadIdx.x;
    if (i < N_NODES) g_deg[i] = 0;
}
__global__ void k_hist(const int* __restrict__ dst) {
    int e = blockIdx.x * blockDim.x + threadIdx.x;
    if (e < N_EDGES) atomicAdd(&g_deg[dst[e]], 1);
}
__global__ void k_scan1() {
    __shared__ int sh[1024];
    int b = blockIdx.x, t = threadIdx.x;
    int i = b * 1024 + t;
    int v = (i < N_NODES) ? g_deg[i] : 0;
    sh[t] = v;
    __syncthreads();
    #pragma unroll
    for (int off = 1; off < 1024; off <<= 1) {
        int x = (t >= off) ? sh[t - off] : 0;
        __syncthreads();
        sh[t] += x;
        __syncthreads();
    }
    if (i < N_NODES) g_rowptr[i] = sh[t] - v;
    if (t == 1023) g_bsum[b] = sh[1023];
}
__global__ void k_scan2(int nblocks) {
    __shared__ int sh[128];
    int t = threadIdx.x;
    int v = (t < nblocks) ? g_bsum[t] : 0;
    sh[t] = v;
    __syncthreads();
    #pragma unroll
    for (int off = 1; off < 128; off <<= 1) {
        int x = (t >= off) ? sh[t - off] : 0;
        __syncthreads();
        sh[t] += x;
        __syncthreads();
    }
    g_boff[t] = sh[t] - v;
    if (t == nblocks - 1) g_boff[128] = sh[t];
}
__global__ void k_scan3() {
    int b = blockIdx.x, t = threadIdx.x;
    int i = b * 1024 + t;
    if (i < N_NODES) {
        int rp = g_rowptr[i] + g_boff[b];
        g_rowptr[i] = rp;
        g_cursor[i] = rp;
        g_invdeg[i] = 1.0f / fmaxf((float)g_deg[i], 1.0f);
    }
    if (b == 0 && t == 0) g_rowptr[N_NODES] = g_boff[128];
}
// scatter + per-edge coefficients for BOTH layers (no eid indirection)
__global__ void k_scatter(const int* __restrict__ dst, const int* __restrict__ src,
                          const int* __restrict__ etype, const float* __restrict__ enorm,
                          const float4* __restrict__ att1, const float4* __restrict__ att2) {
    int e = blockIdx.x * blockDim.x + threadIdx.x;
    if (e >= N_EDGES) return;
    int pos = atomicAdd(&g_cursor[dst[e]], 1);
    g_csr_src[pos] = src[e];
    int t = etype[e];
    float n = enorm[e];
    float4 a1 = att1[t];
    float4 a2 = att2[t];
    g_coeff1[pos] = make_float4(a1.x * n, a1.y * n, a1.z * n, a1.w * n);
    g_coeff2[pos] = make_float4(a2.x * n, a2.y * n, a2.z * n, a2.w * n);
}

// ---------------- embedding gather: h0 fp32 + A1 root cols bf16 ----------------
__global__ void k_gather(const int* __restrict__ entity, const float4* __restrict__ tbl) {
    int t = blockIdx.x * blockDim.x + threadIdx.x;
    if (t >= N_NODES * 32) return;
    int node = t >> 5;
    int lane = t & 31;
    int ent = entity[node];
    float4 v = tbl[(size_t)ent * 32 + lane];
    ((float4*)g_h0)[(size_t)node * 32 + lane] = v;
    size_t a = (size_t)node * KTOT + 512 + 4 * lane;
    *(uint2*)(g_A1hi + a) = make_uint2(pack_hi(v.x, v.y), pack_hi(v.z, v.w));
    *(uint2*)(g_A1lo + a) = make_uint2(pack_lo(v.x, v.y), pack_lo(v.z, v.w));
}

// ---------------- aggregation: warp per dst node, edge metadata preloaded ----------------
__device__ __forceinline__ void agg_fma(float4& s0, float4& s1, float4& s2, float4& s3,
                                        float cx, float cy, float cz, float cw,
                                        const float4& xv) {
    s0.x = fmaf(cx, xv.x, s0.x); s0.y = fmaf(cx, xv.y, s0.y);
    s0.z = fmaf(cx, xv.z, s0.z); s0.w = fmaf(cx, xv.w, s0.w);
    s1.x = fmaf(cy, xv.x, s1.x); s1.y = fmaf(cy, xv.y, s1.y);
    s1.z = fmaf(cy, xv.z, s1.z); s1.w = fmaf(cy, xv.w, s1.w);
    s2.x = fmaf(cz, xv.x, s2.x); s2.y = fmaf(cz, xv.y, s2.y);
    s2.z = fmaf(cz, xv.z, s2.z); s2.w = fmaf(cz, xv.w, s2.w);
    s3.x = fmaf(cw, xv.x, s3.x); s3.y = fmaf(cw, xv.y, s3.y);
    s3.z = fmaf(cw, xv.z, s3.z); s3.w = fmaf(cw, xv.w, s3.w);
}

__global__ void k_agg(int layer) {
    int gw = (blockIdx.x * blockDim.x + threadIdx.x) >> 5;
    int lane = threadIdx.x & 31;
    if (gw >= N_NODES) return;
    const float4* X4 = (const float4*)(layer == 0 ? g_h0 : g_h1);
    const float4* cf = (layer == 0) ? g_coeff1 : g_coeff2;
    __nv_bfloat16* Ahi = (layer == 0) ? g_A1hi : g_A2hi;
    __nv_bfloat16* Alo = (layer == 0) ? g_A1lo : g_A2lo;
    int beg = g_rowptr[gw], end = g_rowptr[gw + 1];
    float4 s0 = make_float4(0.f, 0.f, 0.f, 0.f);
    float4 s1 = s0, s2 = s0, s3 = s0;

    for (int base = beg; base < end; base += 32) {
        int n = end - base; if (n > 32) n = 32;
        // preload this chunk's edge metadata into lane registers
        float4 cl = make_float4(0.f, 0.f, 0.f, 0.f);
        int sl = 0;
        if (lane < n) { cl = cf[base + lane]; sl = g_csr_src[base + lane]; }
        int j = 0;
        for (; j + 4 <= n; j += 4) {
            int n0 = __shfl_sync(0xffffffffu, sl, j);
            int n1 = __shfl_sync(0xffffffffu, sl, j + 1);
            int n2 = __shfl_sync(0xffffffffu, sl, j + 2);
            int n3 = __shfl_sync(0xffffffffu, sl, j + 3);
            float4 x0 = X4[(size_t)n0 * 32 + lane];
            float4 x1 = X4[(size_t)n1 * 32 + lane];
            float4 x2 = X4[(size_t)n2 * 32 + lane];
            float4 x3 = X4[(size_t)n3 * 32 + lane];
            agg_fma(s0, s1, s2, s3,
                    __shfl_sync(0xffffffffu, cl.x, j), __shfl_sync(0xffffffffu, cl.y, j),
                    __shfl_sync(0xffffffffu, cl.z, j), __shfl_sync(0xffffffffu, cl.w, j), x0);
            agg_fma(s0, s1, s2, s3,
                    __shfl_sync(0xffffffffu, cl.x, j + 1), __shfl_sync(0xffffffffu, cl.y, j + 1),
                    __shfl_sync(0xffffffffu, cl.z, j + 1), __shfl_sync(0xffffffffu, cl.w, j + 1), x1);
            agg_fma(s0, s1, s2, s3,
                    __shfl_sync(0xffffffffu, cl.x, j + 2), __shfl_sync(0xffffffffu, cl.y, j + 2),
                    __shfl_sync(0xffffffffu, cl.z, j + 2), __shfl_sync(0xffffffffu, cl.w, j + 2), x2);
            agg_fma(s0, s1, s2, s3,
                    __shfl_sync(0xffffffffu, cl.x, j + 3), __shfl_sync(0xffffffffu, cl.y, j + 3),
                    __shfl_sync(0xffffffffu, cl.z, j + 3), __shfl_sync(0xffffffffu, cl.w, j + 3), x3);
        }
        for (; j < n; ++j) {
            int sn = __shfl_sync(0xffffffffu, sl, j);
            float4 xv = X4[(size_t)sn * 32 + lane];
            agg_fma(s0, s1, s2, s3,
                    __shfl_sync(0xffffffffu, cl.x, j), __shfl_sync(0xffffffffu, cl.y, j),
                    __shfl_sync(0xffffffffu, cl.z, j), __shfl_sync(0xffffffffu, cl.w, j), xv);
        }
    }

    float d = g_invdeg[gw];
    s0.x *= d; s0.y *= d; s0.z *= d; s0.w *= d;
    s1.x *= d; s1.y *= d; s1.z *= d; s1.w *= d;
    s2.x *= d; s2.y *= d; s2.z *= d; s2.w *= d;
    s3.x *= d; s3.y *= d; s3.z *= d; s3.w *= d;
    size_t base = (size_t)gw * KTOT + 4 * lane;
    *(uint2*)(Ahi + base)       = make_uint2(pack_hi(s0.x, s0.y), pack_hi(s0.z, s0.w));
    *(uint2*)(Alo + base)       = make_uint2(pack_lo(s0.x, s0.y), pack_lo(s0.z, s0.w));
    *(uint2*)(Ahi + base + 128) = make_uint2(pack_hi(s1.x, s1.y), pack_hi(s1.z, s1.w));
    *(uint2*)(Alo + base + 128) = make_uint2(pack_lo(s1.x, s1.y), pack_lo(s1.z, s1.w));
    *(uint2*)(Ahi + base + 256) = make_uint2(pack_hi(s2.x, s2.y), pack_hi(s2.z, s2.w));
    *(uint2*)(Alo + base + 256) = make_uint2(pack_lo(s2.x, s2.y), pack_lo(s2.z, s2.w));
    *(uint2*)(Ahi + base + 384) = make_uint2(pack_hi(s3.x, s3.y), pack_hi(s3.z, s3.w));
    *(uint2*)(Alo + base + 384) = make_uint2(pack_lo(s3.x, s3.y), pack_lo(s3.z, s3.w));
}

// ---------------- weight split: W[k][n] -> Whi/Wlo [n][k] bf16 ----------------
__global__ void k_prepw(const float* __restrict__ basis, const float* __restrict__ root) {
    int idx = blockIdx.x * blockDim.x + threadIdx.x;
    if (idx >= 128 * KTOT) return;
    int n = idx / KTOT;
    int k = idx % KTOT;
    float w = (k < 512) ? basis[(size_t)k * 128 + n] : root[(size_t)(k - 512) * 128 + n];
    __nv_bfloat16 hi = __float2bfloat16(w);
    __nv_bfloat16 lo = __float2bfloat16(w - __bfloat162float(hi));
    g_Whi[n * KTOT + k] = hi;
    g_Wlo[n * KTOT + k] = lo;
}

// ---------------- HMMA GEMM, cp.async double-buffered (R4-proven) ----------------
#define TILE_B 10240
#define BUF_B  (4 * TILE_B)
#define SMEM_GEMM (2 * BUF_B)   // 81920 -> 2 CTAs/SM

__global__ __launch_bounds__(256) void k_gemm_mma(
    int layer, const float* __restrict__ bias, float* __restrict__ out_param, int do_relu)
{
    extern __shared__ char smem[];
    uint32_t sbase = smem_u32(smem);
    const __nv_bfloat16* Ahi = (layer == 0) ? g_A1hi : g_A2hi;
    const __nv_bfloat16* Alo = (layer == 0) ? g_A1lo : g_A2lo;
    float* out = (layer == 0) ? g_h1 : out_param;

    int tid = threadIdx.x;
    int wid = tid >> 5;
    int lane = tid & 31;
    int bm = blockIdx.x * 128;
    int wm0 = (wid >> 2) * 64;
    int wn0 = (wid & 3) * 32;

    float acc[4][4][4];
    #pragma unroll
    for (int i = 0; i < 4; i++)
        #pragma unroll
        for (int j = 0; j < 4; j++)
            #pragma unroll
            for (int q = 0; q < 4; q++) acc[i][j][q] = 0.f;

    int lr = tid >> 1;
    int lc0 = (tid & 1) * 2;
    int gmr = bm + lr; if (gmr >= N_NODES) gmr = 0;
    uint32_t a_off = (uint32_t)(lane & 15) * 80 + (uint32_t)(lane >> 4) * 16;
    int bg = lane >> 3;
    uint32_t b_off = (uint32_t)((bg >> 1) * 8 + (lane & 7)) * 80 + (uint32_t)(bg & 1) * 16;

    auto load_chunk = [&](int ch, int buf) {
        int kc = ch * 32;
        uint32_t bo = sbase + buf * BUF_B;
        uint32_t drow = (uint32_t)lr * 80;
        #pragma unroll
        for (int c = 0; c < 2; c++) {
            int cc = lc0 + c;
            uint32_t dof = drow + cc * 16;
            int eof = kc + cc * 8;
            cp16(bo + dof,              Ahi + (size_t)gmr * KTOT + eof);
            cp16(bo + TILE_B + dof,     Alo + (size_t)gmr * KTOT + eof);
            cp16(bo + 2 * TILE_B + dof, g_Whi + lr * KTOT + eof);
            cp16(bo + 3 * TILE_B + dof, g_Wlo + lr * KTOT + eof);
        }
    };

    load_chunk(0, 0);
    CP_COMMIT();

    #pragma unroll 1
    for (int ch = 0; ch < 20; ch++) {
        int buf = ch & 1;
        if (ch < 19) {
            load_chunk(ch + 1, buf ^ 1);
            CP_COMMIT();
            CP_WAIT(1);
        } else {
            CP_WAIT(0);
        }
        __syncthreads();

        uint32_t a_hi_base = sbase + buf * BUF_B;
        uint32_t a_lo_base = a_hi_base + TILE_B;
        uint32_t b_hi_base = a_hi_base + 2 * TILE_B;
        uint32_t b_lo_base = a_hi_base + 3 * TILE_B;

        #pragma unroll
        for (int kk = 0; kk < 2; kk++) {
            uint32_t kb = (uint32_t)kk * 32;
            uint32_t ahi[4][4], alo[4][4];
            #pragma unroll
            for (int mf = 0; mf < 4; mf++) {
                uint32_t o = (uint32_t)(wm0 + mf * 16) * 80 + a_off + kb;
                ldm_x4(ahi[mf], a_hi_base + o);
                ldm_x4(alo[mf], a_lo_base + o);
            }
            uint32_t bhi[4][2], blo[4][2];
            #pragma unroll
            for (int pr = 0; pr < 2; pr++) {
                uint32_t o = (uint32_t)(wn0 + pr * 16) * 80 + b_off + kb;
                uint32_t th[4], tl[4];
                ldm_x4(th, b_hi_base + o);
                ldm_x4(tl, b_lo_base + o);
                bhi[pr * 2][0] = th[0]; bhi[pr * 2][1] = th[1];
                bhi[pr * 2 + 1][0] = th[2]; bhi[pr * 2 + 1][1] = th[3];
                blo[pr * 2][0] = tl[0]; blo[pr * 2][1] = tl[1];
                blo[pr * 2 + 1][0] = tl[2]; blo[pr * 2 + 1][1] = tl[3];
            }
            #pragma unroll
            for (int mf = 0; mf < 4; mf++)
                #pragma unroll
                for (int nf = 0; nf < 4; nf++) {
                    mma16816(acc[mf][nf], ahi[mf], bhi[nf]);
                    mma16816(acc[mf][nf], ahi[mf], blo[nf]);
                    mma16816(acc[mf][nf], alo[mf], bhi[nf]);
                }
        }
        __syncthreads();
    }

    int qm = lane >> 2;
    int qn = (lane & 3) * 2;
    #pragma unroll
    for (int nf = 0; nf < 4; nf++) {
        int n = wn0 + nf * 8 + qn;
        float b0 = bias[n], b1 = bias[n + 1];
        #pragma unroll
        for (int mf = 0; mf < 4; mf++) {
            int m0 = bm + wm0 + mf * 16 + qm;
            float2 lo = make_float2(acc[mf][nf][0] + b0, acc[mf][nf][1] + b1);
            float2 hi = make_float2(acc[mf][nf][2] + b0, acc[mf][nf][3] + b1);
            if (do_relu) {
                lo.x = fmaxf(lo.x, 0.f); lo.y = fmaxf(lo.y, 0.f);
                hi.x = fmaxf(hi.x, 0.f); hi.y = fmaxf(hi.y, 0.f);
            }
            if (m0 < N_NODES) {
                *(float2*)(out + (size_t)m0 * 128 + n) = lo;
                if (layer == 0) {
                    size_t a = (size_t)m0 * KTOT + 512 + n;
                    *(uint32_t*)(g_A2hi + a) = pack_hi(lo.x, lo.y);
                    *(uint32_t*)(g_A2lo + a) = pack_lo(lo.x, lo.y);
                }
            }
            if (m0 + 8 < N_NODES) {
                *(float2*)(out + (size_t)(m0 + 8) * 128 + n) = hi;
                if (layer == 0) {
                    size_t a = (size_t)(m0 + 8) * KTOT + 512 + n;
                    *(uint32_t*)(g_A2hi + a) = pack_hi(hi.x, hi.y);
                    *(uint32_t*)(g_A2lo + a) = pack_lo(hi.x, hi.y);
                }
            }
        }
    }
}

// ---------------- relation_emb passthrough ----------------
__global__ void k_copyrel(const float* __restrict__ rel, float* __restrict__ out) {
    int i = blockIdx.x * blockDim.x + threadIdx.x;
    if (i < 500 * 128) out[i] = rel[i];
}

// ---------------- launch ----------------
extern "C" void kernel_launch(void* const* d_in, const int* in_sizes, int n_in,
                              void* d_out, int out_size) {
    const int*   entity       = (const int*)d_in[0];
    const int*   edge_index   = (const int*)d_in[1];
    const int*   edge_type    = (const int*)d_in[2];
    const float* edge_norm    = (const float*)d_in[3];
    // d_in[4] = DAD_rel (unused by reference output)
    const float* entity_table = (const float*)d_in[5];
    const float* relation_emb = (const float*)d_in[6];
    const float* basis1 = (const float*)d_in[7];
    const float* att1   = (const float*)d_in[8];
    const float* root1  = (const float*)d_in[9];
    const float* bias1  = (const float*)d_in[10];
    const float* basis2 = (const float*)d_in[11];
    const float* att2   = (const float*)d_in[12];
    const float* root2  = (const float*)d_in[13];
    const float* bias2  = (const float*)d_in[14];

    const int* src = edge_index;
    const int* dst = edge_index + N_EDGES;
    float* out = (float*)d_out;

    static int smem_set = 0;
    if (!smem_set) {
        cudaFuncSetAttribute(k_gemm_mma, cudaFuncAttributeMaxDynamicSharedMemorySize, SMEM_GEMM);
        smem_set = 1;
    }

    int scan_blocks = (N_NODES + 1023) / 1024;   // 98

    // CSR by dst (+ CSR-ordered coefficients for both layers)
    k_zero_deg<<<(N_NODES + 255) / 256, 256>>>();
    k_hist<<<(N_EDGES + 255) / 256, 256>>>(dst);
    k_scan1<<<scan_blocks, 1024>>>();
    k_scan2<<<1, 128>>>(scan_blocks);
    k_scan3<<<scan_blocks, 1024>>>();
    k_scatter<<<(N_EDGES + 255) / 256, 256>>>(dst, src, edge_type, edge_norm,
                                              (const float4*)att1, (const float4*)att2);

    // h0 = entity_table[entity] (+ A1 root cols)
    k_gather<<<(N_NODES * 32 + 255) / 256, 256>>>(entity, (const float4*)entity_table);

    int gemm_blocks = (N_NODES + 127) / 128;   // 782

    // layer 1 (relu)
    k_agg<<<(N_NODES * 32 + 255) / 256, 256>>>(0);
    k_prepw<<<(128 * KTOT + 255) / 256, 256>>>(basis1, root1);
    k_gemm_mma<<<gemm_blocks, 256, SMEM_GEMM>>>(0, bias1, nullptr, 1);

    // layer 2 (no relu) -> d_out
    k_agg<<<(N_NODES * 32 + 255) / 256, 256>>>(1);
    k_prepw<<<(128 * KTOT + 255) / 256, 256>>>(basis2, root2);
    k_gemm_mma<<<gemm_blocks, 256, SMEM_GEMM>>>(1, bias2, out, 0);

    // append relation_emb
    k_copyrel<<<(500 * 128 + 255) / 256, 256>>>(relation_emb, out + (size_t)N_NODES * DIM);
}

// round 7
// speedup vs baseline: 1.3980x; 1.0387x over previous
#include <cuda_runtime.h>
#include <cuda_bf16.h>
#include <cstdint>

#define N_NODES 100000
#define N_EDGES 600000
#define DIM 128
#define KTOT 640   // 512 (4 bases x 128) + 128 (root)

// ---------------- scratch (static device globals; no runtime alloc) ----------------
__device__ float g_h0[(size_t)N_NODES * DIM];
__device__ float g_h1[(size_t)N_NODES * DIM];
__device__ __nv_bfloat16 g_A1hi[(size_t)N_NODES * KTOT];  // layer-1 GEMM A = [S1 | h0]
__device__ __nv_bfloat16 g_A1lo[(size_t)N_NODES * KTOT];
__device__ __nv_bfloat16 g_A2hi[(size_t)N_NODES * KTOT];  // layer-2 GEMM A = [S2 | h1]
__device__ __nv_bfloat16 g_A2lo[(size_t)N_NODES * KTOT];
__device__ float4 g_coeff1[N_EDGES];          // CSR-ordered, layer 1
__device__ float4 g_coeff2[N_EDGES];          // CSR-ordered, layer 2
__device__ int   g_csr_src[N_EDGES];
__device__ int   g_deg[N_NODES];
__device__ int   g_rowptr[N_NODES + 1];
__device__ int   g_cursor[N_NODES];
__device__ float g_invdeg[N_NODES];
__device__ int   g_bsum[128];
__device__ int   g_boff[129];
__device__ __nv_bfloat16 g_Whi[128 * KTOT];   // [n][k]
__device__ __nv_bfloat16 g_Wlo[128 * KTOT];   // [n][k]

// ---------------- helpers ----------------
__device__ __forceinline__ uint32_t smem_u32(const void* p) {
    uint32_t a;
    asm("{ .reg .u64 t; cvta.to.shared.u64 t, %1; cvt.u32.u64 %0, t; }" : "=r"(a) : "l"(p));
    return a;
}
__device__ __forceinline__ void ldm_x4(uint32_t* r, uint32_t addr) {
    asm volatile("ldmatrix.sync.aligned.m8n8.x4.shared.b16 {%0,%1,%2,%3}, [%4];"
                 : "=r"(r[0]), "=r"(r[1]), "=r"(r[2]), "=r"(r[3]) : "r"(addr));
}
__device__ __forceinline__ void mma16816(float* c, const uint32_t* a, const uint32_t* b) {
    asm volatile("mma.sync.aligned.m16n8k16.row.col.f32.bf16.bf16.f32 "
                 "{%0,%1,%2,%3}, {%4,%5,%6,%7}, {%8,%9}, {%0,%1,%2,%3};"
                 : "+f"(c[0]), "+f"(c[1]), "+f"(c[2]), "+f"(c[3])
                 : "r"(a[0]), "r"(a[1]), "r"(a[2]), "r"(a[3]), "r"(b[0]), "r"(b[1]));
}
__device__ __forceinline__ void cp16(uint32_t dst, const void* src) {
    asm volatile("cp.async.cg.shared.global [%0], [%1], 16;" :: "r"(dst), "l"(src));
}
#define CP_COMMIT() asm volatile("cp.async.commit_group;" ::: "memory")
#define CP_WAIT(N)  asm volatile("cp.async.wait_group %0;" :: "n"(N) : "memory")

__device__ __forceinline__ uint32_t pack_hi(float a, float b) {
    __nv_bfloat16 ha = __float2bfloat16(a), hb = __float2bfloat16(b);
    return (uint32_t)__bfloat16_as_ushort(ha) | ((uint32_t)__bfloat16_as_ushort(hb) << 16);
}
__device__ __forceinline__ uint32_t pack_lo(float a, float b) {
    __nv_bfloat16 ha = __float2bfloat16(a), hb = __float2bfloat16(b);
    __nv_bfloat16 la = __float2bfloat16(a - __bfloat162float(ha));
    __nv_bfloat16 lb = __float2bfloat16(b - __bfloat162float(hb));
    return (uint32_t)__bfloat16_as_ushort(la) | ((uint32_t)__bfloat16_as_ushort(lb) << 16);
}

// ---------------- CSR build ----------------
__global__ void k_zero_deg() {
    int i = blockIdx.x * blockDim.x + threadIdx.x;
    if (i < N_NODES) g_deg[i] = 0;
}
__global__ void k_hist(const int* __restrict__ dst) {
    int e = blockIdx.x * blockDim.x + threadIdx.x;
    if (e < N_EDGES) atomicAdd(&g_deg[dst[e]], 1);
}
__global__ void k_scan1() {
    __shared__ int sh[1024];
    int b = blockIdx.x, t = threadIdx.x;
    int i = b * 1024 + t;
    int v = (i < N_NODES) ? g_deg[i] : 0;
    sh[t] = v;
    __syncthreads();
    #pragma unroll
    for (int off = 1; off < 1024; off <<= 1) {
        int x = (t >= off) ? sh[t - off] : 0;
        __syncthreads();
        sh[t] += x;
        __syncthreads();
    }
    if (i < N_NODES) g_rowptr[i] = sh[t] - v;
    if (t == 1023) g_bsum[b] = sh[1023];
}
__global__ void k_scan2(int nblocks) {
    __shared__ int sh[128];
    int t = threadIdx.x;
    int v = (t < nblocks) ? g_bsum[t] : 0;
    sh[t] = v;
    __syncthreads();
    #pragma unroll
    for (int off = 1; off < 128; off <<= 1) {
        int x = (t >= off) ? sh[t - off] : 0;
        __syncthreads();
        sh[t] += x;
        __syncthreads();
    }
    g_boff[t] = sh[t] - v;
    if (t == nblocks - 1) g_boff[128] = sh[t];
}
__global__ void k_scan3() {
    int b = blockIdx.x, t = threadIdx.x;
    int i = b * 1024 + t;
    if (i < N_NODES) {
        int rp = g_rowptr[i] + g_boff[b];
        g_rowptr[i] = rp;
        g_cursor[i] = rp;
        g_invdeg[i] = 1.0f / fmaxf((float)g_deg[i], 1.0f);
    }
    if (b == 0 && t == 0) g_rowptr[N_NODES] = g_boff[128];
}
// scatter + per-edge coefficients for BOTH layers (no eid indirection)
__global__ void k_scatter(const int* __restrict__ dst, const int* __restrict__ src,
                          const int* __restrict__ etype, const float* __restrict__ enorm,
                          const float4* __restrict__ att1, const float4* __restrict__ att2) {
    int e = blockIdx.x * blockDim.x + threadIdx.x;
    if (e >= N_EDGES) return;
    int pos = atomicAdd(&g_cursor[dst[e]], 1);
    g_csr_src[pos] = src[e];
    int t = etype[e];
    float n = enorm[e];
    float4 a1 = att1[t];
    float4 a2 = att2[t];
    g_coeff1[pos] = make_float4(a1.x * n, a1.y * n, a1.z * n, a1.w * n);
    g_coeff2[pos] = make_float4(a2.x * n, a2.y * n, a2.z * n, a2.w * n);
}

// ---------------- embedding gather: h0 fp32 + A1 root cols bf16 ----------------
__global__ void k_gather(const int* __restrict__ entity, const float4* __restrict__ tbl) {
    int t = blockIdx.x * blockDim.x + threadIdx.x;
    if (t >= N_NODES * 32) return;
    int node = t >> 5;
    int lane = t & 31;
    int ent = entity[node];
    float4 v = tbl[(size_t)ent * 32 + lane];
    ((float4*)g_h0)[(size_t)node * 32 + lane] = v;
    size_t a = (size_t)node * KTOT + 512 + 4 * lane;
    *(uint2*)(g_A1hi + a) = make_uint2(pack_hi(v.x, v.y), pack_hi(v.z, v.w));
    *(uint2*)(g_A1lo + a) = make_uint2(pack_lo(v.x, v.y), pack_lo(v.z, v.w));
}

// ---------------- aggregation: warp per dst node (R4-proven direct loads) ----------------
__global__ void k_agg(int layer) {
    int gw = (blockIdx.x * blockDim.x + threadIdx.x) >> 5;
    int lane = threadIdx.x & 31;
    if (gw >= N_NODES) return;
    const float4* x4 = (const float4*)(layer == 0 ? g_h0 : g_h1);
    const float4* cf = (layer == 0) ? g_coeff1 : g_coeff2;
    __nv_bfloat16* Ahi = (layer == 0) ? g_A1hi : g_A2hi;
    __nv_bfloat16* Alo = (layer == 0) ? g_A1lo : g_A2lo;
    int beg = g_rowptr[gw], end = g_rowptr[gw + 1];
    float4 s0 = make_float4(0.f, 0.f, 0.f, 0.f);
    float4 s1 = s0, s2 = s0, s3 = s0;
    int p = beg;
    for (; p + 2 <= end; p += 2) {
        float4 ca = cf[p];
        float4 cb = cf[p + 1];
        int sa = g_csr_src[p];
        int sb = g_csr_src[p + 1];
        float4 xa = x4[(size_t)sa * 32 + lane];
        float4 xb = x4[(size_t)sb * 32 + lane];
        s0.x = fmaf(ca.x, xa.x, s0.x); s0.y = fmaf(ca.x, xa.y, s0.y);
        s0.z = fmaf(ca.x, xa.z, s0.z); s0.w = fmaf(ca.x, xa.w, s0.w);
        s1.x = fmaf(ca.y, xa.x, s1.x); s1.y = fmaf(ca.y, xa.y, s1.y);
        s1.z = fmaf(ca.y, xa.z, s1.z); s1.w = fmaf(ca.y, xa.w, s1.w);
        s2.x = fmaf(ca.z, xa.x, s2.x); s2.y = fmaf(ca.z, xa.y, s2.y);
        s2.z = fmaf(ca.z, xa.z, s2.z); s2.w = fmaf(ca.z, xa.w, s2.w);
        s3.x = fmaf(ca.w, xa.x, s3.x); s3.y = fmaf(ca.w, xa.y, s3.y);
        s3.z = fmaf(ca.w, xa.z, s3.z); s3.w = fmaf(ca.w, xa.w, s3.w);
        s0.x = fmaf(cb.x, xb.x, s0.x); s0.y = fmaf(cb.x, xb.y, s0.y);
        s0.z = fmaf(cb.x, xb.z, s0.z); s0.w = fmaf(cb.x, xb.w, s0.w);
        s1.x = fmaf(cb.y, xb.x, s1.x); s1.y = fmaf(cb.y, xb.y, s1.y);
        s1.z = fmaf(cb.y, xb.z, s1.z); s1.w = fmaf(cb.y, xb.w, s1.w);
        s2.x = fmaf(cb.z, xb.x, s2.x); s2.y = fmaf(cb.z, xb.y, s2.y);
        s2.z = fmaf(cb.z, xb.z, s2.z); s2.w = fmaf(cb.z, xb.w, s2.w);
        s3.x = fmaf(cb.w, xb.x, s3.x); s3.y = fmaf(cb.w, xb.y, s3.y);
        s3.z = fmaf(cb.w, xb.z, s3.z); s3.w = fmaf(cb.w, xb.w, s3.w);
    }
    if (p < end) {
        float4 c = cf[p];
        int sn = g_csr_src[p];
        float4 xv = x4[(size_t)sn * 32 + lane];
        s0.x = fmaf(c.x, xv.x, s0.x); s0.y = fmaf(c.x, xv.y, s0.y);
        s0.z = fmaf(c.x, xv.z, s0.z); s0.w = fmaf(c.x, xv.w, s0.w);
        s1.x = fmaf(c.y, xv.x, s1.x); s1.y = fmaf(c.y, xv.y, s1.y);
        s1.z = fmaf(c.y, xv.z, s1.z); s1.w = fmaf(c.y, xv.w, s1.w);
        s2.x = fmaf(c.z, xv.x, s2.x); s2.y = fmaf(c.z, xv.y, s2.y);
        s2.z = fmaf(c.z, xv.z, s2.z); s2.w = fmaf(c.z, xv.w, s2.w);
        s3.x = fmaf(c.w, xv.x, s3.x); s3.y = fmaf(c.w, xv.y, s3.y);
        s3.z = fmaf(c.w, xv.z, s3.z); s3.w = fmaf(c.w, xv.w, s3.w);
    }
    float d = g_invdeg[gw];
    s0.x *= d; s0.y *= d; s0.z *= d; s0.w *= d;
    s1.x *= d; s1.y *= d; s1.z *= d; s1.w *= d;
    s2.x *= d; s2.y *= d; s2.z *= d; s2.w *= d;
    s3.x *= d; s3.y *= d; s3.z *= d; s3.w *= d;
    size_t base = (size_t)gw * KTOT + 4 * lane;
    *(uint2*)(Ahi + base)       = make_uint2(pack_hi(s0.x, s0.y), pack_hi(s0.z, s0.w));
    *(uint2*)(Alo + base)       = make_uint2(pack_lo(s0.x, s0.y), pack_lo(s0.z, s0.w));
    *(uint2*)(Ahi + base + 128) = make_uint2(pack_hi(s1.x, s1.y), pack_hi(s1.z, s1.w));
    *(uint2*)(Alo + base + 128) = make_uint2(pack_lo(s1.x, s1.y), pack_lo(s1.z, s1.w));
    *(uint2*)(Ahi + base + 256) = make_uint2(pack_hi(s2.x, s2.y), pack_hi(s2.z, s2.w));
    *(uint2*)(Alo + base + 256) = make_uint2(pack_lo(s2.x, s2.y), pack_lo(s2.z, s2.w));
    *(uint2*)(Ahi + base + 384) = make_uint2(pack_hi(s3.x, s3.y), pack_hi(s3.z, s3.w));
    *(uint2*)(Alo + base + 384) = make_uint2(pack_lo(s3.x, s3.y), pack_lo(s3.z, s3.w));
}

// ---------------- weight split: W[k][n] -> Whi/Wlo [n][k] bf16 ----------------
__global__ void k_prepw(const float* __restrict__ basis, const float* __restrict__ root) {
    int idx = blockIdx.x * blockDim.x + threadIdx.x;
    if (idx >= 128 * KTOT) return;
    int n = idx / KTOT;
    int k = idx % KTOT;
    float w = (k < 512) ? basis[(size_t)k * 128 + n] : root[(size_t)(k - 512) * 128 + n];
    __nv_bfloat16 hi = __float2bfloat16(w);
    __nv_bfloat16 lo = __float2bfloat16(w - __bfloat162float(hi));
    g_Whi[n * KTOT + k] = hi;
    g_Wlo[n * KTOT + k] = lo;
}

// ---------------- HMMA GEMM, cp.async double-buffered (R4-proven) ----------------
#define TILE_B 10240
#define BUF_B  (4 * TILE_B)
#define SMEM_GEMM (2 * BUF_B)   // 81920 -> 2 CTAs/SM

__global__ __launch_bounds__(256) void k_gemm_mma(
    int layer, const float* __restrict__ bias, float* __restrict__ out_param, int do_relu)
{
    extern __shared__ char smem[];
    uint32_t sbase = smem_u32(smem);
    const __nv_bfloat16* Ahi = (layer == 0) ? g_A1hi : g_A2hi;
    const __nv_bfloat16* Alo = (layer == 0) ? g_A1lo : g_A2lo;
    float* out = (layer == 0) ? g_h1 : out_param;

    int tid = threadIdx.x;
    int wid = tid >> 5;
    int lane = tid & 31;
    int bm = blockIdx.x * 128;
    int wm0 = (wid >> 2) * 64;
    int wn0 = (wid & 3) * 32;

    float acc[4][4][4];
    #pragma unroll
    for (int i = 0; i < 4; i++)
        #pragma unroll
        for (int j = 0; j < 4; j++)
            #pragma unroll
            for (int q = 0; q < 4; q++) acc[i][j][q] = 0.f;

    int lr = tid >> 1;
    int lc0 = (tid & 1) * 2;
    int gmr = bm + lr; if (gmr >= N_NODES) gmr = 0;
    uint32_t a_off = (uint32_t)(lane & 15) * 80 + (uint32_t)(lane >> 4) * 16;
    int bg = lane >> 3;
    uint32_t b_off = (uint32_t)((bg >> 1) * 8 + (lane & 7)) * 80 + (uint32_t)(bg & 1) * 16;

    auto load_chunk = [&](int ch, int buf) {
        int kc = ch * 32;
        uint32_t bo = sbase + buf * BUF_B;
        uint32_t drow = (uint32_t)lr * 80;
        #pragma unroll
        for (int c = 0; c < 2; c++) {
            int cc = lc0 + c;
            uint32_t dof = drow + cc * 16;
            int eof = kc + cc * 8;
            cp16(bo + dof,              Ahi + (size_t)gmr * KTOT + eof);
            cp16(bo + TILE_B + dof,     Alo + (size_t)gmr * KTOT + eof);
            cp16(bo + 2 * TILE_B + dof, g_Whi + lr * KTOT + eof);
            cp16(bo + 3 * TILE_B + dof, g_Wlo + lr * KTOT + eof);
        }
    };

    load_chunk(0, 0);
    CP_COMMIT();

    #pragma unroll 1
    for (int ch = 0; ch < 20; ch++) {
        int buf = ch & 1;
        if (ch < 19) {
            load_chunk(ch + 1, buf ^ 1);
            CP_COMMIT();
            CP_WAIT(1);
        } else {
            CP_WAIT(0);
        }
        __syncthreads();

        uint32_t a_hi_base = sbase + buf * BUF_B;
        uint32_t a_lo_base = a_hi_base + TILE_B;
        uint32_t b_hi_base = a_hi_base + 2 * TILE_B;
        uint32_t b_lo_base = a_hi_base + 3 * TILE_B;

        #pragma unroll
        for (int kk = 0; kk < 2; kk++) {
            uint32_t kb = (uint32_t)kk * 32;
            uint32_t ahi[4][4], alo[4][4];
            #pragma unroll
            for (int mf = 0; mf < 4; mf++) {
                uint32_t o = (uint32_t)(wm0 + mf * 16) * 80 + a_off + kb;
                ldm_x4(ahi[mf], a_hi_base + o);
                ldm_x4(alo[mf], a_lo_base + o);
            }
            uint32_t bhi[4][2], blo[4][2];
            #pragma unroll
            for (int pr = 0; pr < 2; pr++) {
                uint32_t o = (uint32_t)(wn0 + pr * 16) * 80 + b_off + kb;
                uint32_t th[4], tl[4];
                ldm_x4(th, b_hi_base + o);
                ldm_x4(tl, b_lo_base + o);
                bhi[pr * 2][0] = th[0]; bhi[pr * 2][1] = th[1];
                bhi[pr * 2 + 1][0] = th[2]; bhi[pr * 2 + 1][1] = th[3];
                blo[pr * 2][0] = tl[0]; blo[pr * 2][1] = tl[1];
                blo[pr * 2 + 1][0] = tl[2]; blo[pr * 2 + 1][1] = tl[3];
            }
            #pragma unroll
            for (int mf = 0; mf < 4; mf++)
                #pragma unroll
                for (int nf = 0; nf < 4; nf++) {
                    mma16816(acc[mf][nf], ahi[mf], bhi[nf]);
                    mma16816(acc[mf][nf], ahi[mf], blo[nf]);
                    mma16816(acc[mf][nf], alo[mf], bhi[nf]);
                }
        }
        __syncthreads();
    }

    int qm = lane >> 2;
    int qn = (lane & 3) * 2;
    #pragma unroll
    for (int nf = 0; nf < 4; nf++) {
        int n = wn0 + nf * 8 + qn;
        float b0 = bias[n], b1 = bias[n + 1];
        #pragma unroll
        for (int mf = 0; mf < 4; mf++) {
            int m0 = bm + wm0 + mf * 16 + qm;
            float2 lo = make_float2(acc[mf][nf][0] + b0, acc[mf][nf][1] + b1);
            float2 hi = make_float2(acc[mf][nf][2] + b0, acc[mf][nf][3] + b1);
            if (do_relu) {
                lo.x = fmaxf(lo.x, 0.f); lo.y = fmaxf(lo.y, 0.f);
                hi.x = fmaxf(hi.x, 0.f); hi.y = fmaxf(hi.y, 0.f);
            }
            if (m0 < N_NODES) {
                *(float2*)(out + (size_t)m0 * 128 + n) = lo;
                if (layer == 0) {
                    size_t a = (size_t)m0 * KTOT + 512 + n;
                    *(uint32_t*)(g_A2hi + a) = pack_hi(lo.x, lo.y);
                    *(uint32_t*)(g_A2lo + a) = pack_lo(lo.x, lo.y);
                }
            }
            if (m0 + 8 < N_NODES) {
                *(float2*)(out + (size_t)(m0 + 8) * 128 + n) = hi;
                if (layer == 0) {
                    size_t a = (size_t)(m0 + 8) * KTOT + 512 + n;
                    *(uint32_t*)(g_A2hi + a) = pack_hi(hi.x, hi.y);
                    *(uint32_t*)(g_A2lo + a) = pack_lo(hi.x, hi.y);
                }
            }
        }
    }
}

// ---------------- relation_emb passthrough ----------------
__global__ void k_copyrel(const float* __restrict__ rel, float* __restrict__ out) {
    int i = blockIdx.x * blockDim.x + threadIdx.x;
    if (i < 500 * 128) out[i] = rel[i];
}

// ---------------- launch ----------------
extern "C" void kernel_launch(void* const* d_in, const int* in_sizes, int n_in,
                              void* d_out, int out_size) {
    const int*   entity       = (const int*)d_in[0];
    const int*   edge_index   = (const int*)d_in[1];
    const int*   edge_type    = (const int*)d_in[2];
    const float* edge_norm    = (const float*)d_in[3];
    // d_in[4] = DAD_rel (unused by reference output)
    const float* entity_table = (const float*)d_in[5];
    const float* relation_emb = (const float*)d_in[6];
    const float* basis1 = (const float*)d_in[7];
    const float* att1   = (const float*)d_in[8];
    const float* root1  = (const float*)d_in[9];
    const float* bias1  = (const float*)d_in[10];
    const float* basis2 = (const float*)d_in[11];
    const float* att2   = (const float*)d_in[12];
    const float* root2  = (const float*)d_in[13];
    const float* bias2  = (const float*)d_in[14];

    const int* src = edge_index;
    const int* dst = edge_index + N_EDGES;
    float* out = (float*)d_out;

    static int smem_set = 0;
    if (!smem_set) {
        cudaFuncSetAttribute(k_gemm_mma, cudaFuncAttributeMaxDynamicSharedMemorySize, SMEM_GEMM);
        smem_set = 1;
    }

    int scan_blocks = (N_NODES + 1023) / 1024;   // 98

    // CSR by dst (+ CSR-ordered coefficients for both layers)
    k_zero_deg<<<(N_NODES + 255) / 256, 256>>>();
    k_hist<<<(N_EDGES + 255) / 256, 256>>>(dst);
    k_scan1<<<scan_blocks, 1024>>>();
    k_scan2<<<1, 128>>>(scan_blocks);
    k_scan3<<<scan_blocks, 1024>>>();
    k_scatter<<<(N_EDGES + 255) / 256, 256>>>(dst, src, edge_type, edge_norm,
                                              (const float4*)att1, (const float4*)att2);

    // h0 = entity_table[entity] (+ A1 root cols)
    k_gather<<<(N_NODES * 32 + 255) / 256, 256>>>(entity, (const float4*)entity_table);

    int gemm_blocks = (N_NODES + 127) / 128;   // 782

    // layer 1 (relu)
    k_agg<<<(N_NODES * 32 + 255) / 256, 256>>>(0);
    k_prepw<<<(128 * KTOT + 255) / 256, 256>>>(basis1, root1);
    k_gemm_mma<<<gemm_blocks, 256, SMEM_GEMM>>>(0, bias1, nullptr, 1);

    // layer 2 (no relu) -> d_out
    k_agg<<<(N_NODES * 32 + 255) / 256, 256>>>(1);
    k_prepw<<<(128 * KTOT + 255) / 256, 256>>>(basis2, root2);
    k_gemm_mma<<<gemm_blocks, 256, SMEM_GEMM>>>(1, bias2, out, 0);

    // append relation_emb
    k_copyrel<<<(500 * 128 + 255) / 256, 256>>>(relation_emb, out + (size_t)N_NODES * DIM);
}

// round 8
// speedup vs baseline: 1.4838x; 1.0614x over previous
#include <cuda_runtime.h>
#include <cuda_bf16.h>
#include <cstdint>

#define N_NODES 100000
#define N_EDGES 600000
#define DIM 128
#define KTOT 640   // 512 (4 bases x 128) + 128 (root)
#define SCAN_BLOCKS 98   // ceil(100000/1024)
#define AGG_BLOCKS 12500 // 100000 warps / 8

// ---------------- scratch (static device globals; no runtime alloc) ----------------
__device__ float g_h1[(size_t)N_NODES * DIM];
__device__ __nv_bfloat16 g_A1hi[(size_t)N_NODES * KTOT];  // layer-1 GEMM A = [S1 | h0]
__device__ __nv_bfloat16 g_A1lo[(size_t)N_NODES * KTOT];
__device__ __nv_bfloat16 g_A2hi[(size_t)N_NODES * KTOT];  // layer-2 GEMM A = [S2 | h1]
__device__ __nv_bfloat16 g_A2lo[(size_t)N_NODES * KTOT];
__device__ float4 g_coeff1[N_EDGES];          // CSR-ordered, layer 1
__device__ float4 g_coeff2[N_EDGES];          // CSR-ordered, layer 2
__device__ int   g_csr_src[N_EDGES];          // node index (for h1 gathers)
__device__ int   g_csr_esrc[N_EDGES];         // entity index (for table gathers)
__device__ int   g_deg[N_NODES];
__device__ int   g_rowptr[N_NODES + 1];
__device__ int   g_cursor[N_NODES];
__device__ float g_invdeg[N_NODES];
__device__ unsigned long long g_scan_state[SCAN_BLOCKS];  // (val<<2)|flag, flag:1=agg,2=prefix
__device__ int   g_ticket;
__device__ __nv_bfloat16 g_Whi[128 * KTOT];   // [n][k]
__device__ __nv_bfloat16 g_Wlo[128 * KTOT];   // [n][k]

// ---------------- helpers ----------------
__device__ __forceinline__ uint32_t smem_u32(const void* p) {
    uint32_t a;
    asm("{ .reg .u64 t; cvta.to.shared.u64 t, %1; cvt.u32.u64 %0, t; }" : "=r"(a) : "l"(p));
    return a;
}
__device__ __forceinline__ void ldm_x4(uint32_t* r, uint32_t addr) {
    asm volatile("ldmatrix.sync.aligned.m8n8.x4.shared.b16 {%0,%1,%2,%3}, [%4];"
                 : "=r"(r[0]), "=r"(r[1]), "=r"(r[2]), "=r"(r[3]) : "r"(addr));
}
__device__ __forceinline__ void mma16816(float* c, const uint32_t* a, const uint32_t* b) {
    asm volatile("mma.sync.aligned.m16n8k16.row.col.f32.bf16.bf16.f32 "
                 "{%0,%1,%2,%3}, {%4,%5,%6,%7}, {%8,%9}, {%0,%1,%2,%3};"
                 : "+f"(c[0]), "+f"(c[1]), "+f"(c[2]), "+f"(c[3])
                 : "r"(a[0]), "r"(a[1]), "r"(a[2]), "r"(a[3]), "r"(b[0]), "r"(b[1]));
}
__device__ __forceinline__ void cp16(uint32_t dst, const void* src) {
    asm volatile("cp.async.cg.shared.global [%0], [%1], 16;" :: "r"(dst), "l"(src));
}
#define CP_COMMIT() asm volatile("cp.async.commit_group;" ::: "memory")
#define CP_WAIT(N)  asm volatile("cp.async.wait_group %0;" :: "n"(N) : "memory")

__device__ __forceinline__ uint32_t pack_hi(float a, float b) {
    __nv_bfloat16 ha = __float2bfloat16(a), hb = __float2bfloat16(b);
    return (uint32_t)__bfloat16_as_ushort(ha) | ((uint32_t)__bfloat16_as_ushort(hb) << 16);
}
__device__ __forceinline__ uint32_t pack_lo(float a, float b) {
    __nv_bfloat16 ha = __float2bfloat16(a), hb = __float2bfloat16(b);
    __nv_bfloat16 la = __float2bfloat16(a - __bfloat162float(ha));
    __nv_bfloat16 lb = __float2bfloat16(b - __bfloat162float(hb));
    return (uint32_t)__bfloat16_as_ushort(la) | ((uint32_t)__bfloat16_as_ushort(lb) << 16);
}

// ---------------- 1: zero ----------------
__global__ void k_zero() {
    int i = blockIdx.x * blockDim.x + threadIdx.x;
    if (i < N_NODES) g_deg[i] = 0;
    if (i < SCAN_BLOCKS) g_scan_state[i] = 0ull;
    if (i == 0) { g_ticket = 0; g_rowptr[N_NODES] = N_EDGES; }
}

// ---------------- 2: hist + weight split (both layers) ----------------
__global__ void k_hist_prepw(const int* __restrict__ dst,
                             const float* __restrict__ basis1, const float* __restrict__ root1,
                             const float* __restrict__ basis2, const float* __restrict__ root2) {
    int i = blockIdx.x * blockDim.x + threadIdx.x;
    if (i < N_EDGES) atomicAdd(&g_deg[dst[i]], 1);
    if (i < 2 * 128 * KTOT) {
        int which = i >= 128 * KTOT;
        int idx = which ? i - 128 * KTOT : i;
        int n = idx / KTOT;
        int k = idx % KTOT;
        const float* basis = which ? basis2 : basis1;
        const float* root  = which ? root2  : root1;
        float w = (k < 512) ? basis[(size_t)k * 128 + n] : root[(size_t)(k - 512) * 128 + n];
        __nv_bfloat16 hi = __float2bfloat16(w);
        __nv_bfloat16 lo = __float2bfloat16(w - __bfloat162float(hi));
        __nv_bfloat16* Whi = g_Whi;
        __nv_bfloat16* Wlo = g_Wlo;
        // layer 2 weights appended after layer 1 in the same arrays? No — separate halves:
        // store layer1 at [0, 128*KTOT), layer2 handled via pointer offset at GEMM launch.
        if (which) { Whi += 0; Wlo += 0; }   // placeholder; layer select below
        // NOTE: we keep two separate regions inside one array pair via offset:
        ((__nv_bfloat16*)(which ? g_Whi + 0 : g_Whi))[0] = ((__nv_bfloat16*)(which ? g_Whi : g_Whi))[0];
        // (see g_W2hi/g_W2lo below — simpler)
    }
}

// simpler: distinct arrays for layer 2
__device__ __nv_bfloat16 g_W2hi[128 * KTOT];
__device__ __nv_bfloat16 g_W2lo[128 * KTOT];

__global__ void k_hist_prepw2(const int* __restrict__ dst,
                              const float* __restrict__ basis1, const float* __restrict__ root1,
                              const float* __restrict__ basis2, const float* __restrict__ root2) {
    int i = blockIdx.x * blockDim.x + threadIdx.x;
    if (i < N_EDGES) atomicAdd(&g_deg[dst[i]], 1);
    if (i < 2 * 128 * KTOT) {
        int which = i >= 128 * KTOT;
        int idx = which ? i - 128 * KTOT : i;
        int n = idx / KTOT;
        int k = idx % KTOT;
        const float* basis = which ? basis2 : basis1;
        const float* root  = which ? root2  : root1;
        float w = (k < 512) ? basis[(size_t)k * 128 + n] : root[(size_t)(k - 512) * 128 + n];
        __nv_bfloat16 hi = __float2bfloat16(w);
        __nv_bfloat16 lo = __float2bfloat16(w - __bfloat162float(hi));
        if (which) { g_W2hi[n * KTOT + k] = hi; g_W2lo[n * KTOT + k] = lo; }
        else       { g_Whi[n * KTOT + k]  = hi; g_Wlo[n * KTOT + k]  = lo; }
    }
}

// ---------------- 3: single-pass decoupled-lookback scan ----------------
__global__ void k_scan() {
    __shared__ int sh[1024];
    __shared__ int sbid;
    __shared__ int sexcl;
    int t = threadIdx.x;
    if (t == 0) sbid = atomicAdd(&g_ticket, 1);
    __syncthreads();
    int b = sbid;
    int i = b * 1024 + t;
    int v = (i < N_NODES) ? g_deg[i] : 0;
    sh[t] = v;
    __syncthreads();
    #pragma unroll
    for (int off = 1; off < 1024; off <<= 1) {
        int x = (t >= off) ? sh[t - off] : 0;
        __syncthreads();
        sh[t] += x;
        __syncthreads();
    }
    if (t == 0) {
        int total = sh[1023];
        int excl = 0;
        if (b == 0) {
            atomicExch(&g_scan_state[0], ((unsigned long long)total << 2) | 2ull);
        } else {
            atomicExch(&g_scan_state[b], ((unsigned long long)total << 2) | 1ull);
            int j = b - 1;
            long long run = 0;
            while (true) {
                unsigned long long s = atomicAdd(&g_scan_state[j], 0ull);
                unsigned f = (unsigned)(s & 3ull);
                if (f == 0) continue;          // spin
                run += (long long)(s >> 2);
                if (f == 2) break;
                j--;
            }
            excl = (int)run;
            atomicExch(&g_scan_state[b], ((unsigned long long)(excl + total) << 2) | 2ull);
        }
        sexcl = excl;
    }
    __syncthreads();
    if (i < N_NODES) {
        int rp = sexcl + sh[t] - v;
        g_rowptr[i] = rp;
        g_cursor[i] = rp;
        g_invdeg[i] = 1.0f / fmaxf((float)v, 1.0f);
    }
}

// ---------------- 4: scatter + CSR-ordered coefficients + entity-resolved src ----------------
__global__ void k_scatter(const int* __restrict__ dst, const int* __restrict__ src,
                          const int* __restrict__ entity,
                          const int* __restrict__ etype, const float* __restrict__ enorm,
                          const float4* __restrict__ att1, const float4* __restrict__ att2) {
    int e = blockIdx.x * blockDim.x + threadIdx.x;
    if (e >= N_EDGES) return;
    int s = src[e];
    int pos = atomicAdd(&g_cursor[dst[e]], 1);
    g_csr_src[pos] = s;
    g_csr_esrc[pos] = entity[s];
    int t = etype[e];
    float n = enorm[e];
    float4 a1 = att1[t];
    float4 a2 = att2[t];
    g_coeff1[pos] = make_float4(a1.x * n, a1.y * n, a1.z * n, a1.w * n);
    g_coeff2[pos] = make_float4(a2.x * n, a2.y * n, a2.z * n, a2.w * n);
}

// ---------------- aggregation core (R4-proven direct loads) ----------------
__device__ __forceinline__ void agg_node(int node, int lane,
                                         const float4* __restrict__ X4,
                                         const int* __restrict__ sidx,
                                         const float4* __restrict__ cf,
                                         float4& s0, float4& s1, float4& s2, float4& s3) {
    int beg = g_rowptr[node], end = g_rowptr[node + 1];
    int p = beg;
    for (; p + 2 <= end; p += 2) {
        float4 ca = cf[p];
        float4 cb = cf[p + 1];
        int sa = sidx[p];
        int sb = sidx[p + 1];
        float4 xa = X4[(size_t)sa * 32 + lane];
        float4 xb = X4[(size_t)sb * 32 + lane];
        s0.x = fmaf(ca.x, xa.x, s0.x); s0.y = fmaf(ca.x, xa.y, s0.y);
        s0.z = fmaf(ca.x, xa.z, s0.z); s0.w = fmaf(ca.x, xa.w, s0.w);
        s1.x = fmaf(ca.y, xa.x, s1.x); s1.y = fmaf(ca.y, xa.y, s1.y);
        s1.z = fmaf(ca.y, xa.z, s1.z); s1.w = fmaf(ca.y, xa.w, s1.w);
        s2.x = fmaf(ca.z, xa.x, s2.x); s2.y = fmaf(ca.z, xa.y, s2.y);
        s2.z = fmaf(ca.z, xa.z, s2.z); s2.w = fmaf(ca.z, xa.w, s2.w);
        s3.x = fmaf(ca.w, xa.x, s3.x); s3.y = fmaf(ca.w, xa.y, s3.y);
        s3.z = fmaf(ca.w, xa.z, s3.z); s3.w = fmaf(ca.w, xa.w, s3.w);
        s0.x = fmaf(cb.x, xb.x, s0.x); s0.y = fmaf(cb.x, xb.y, s0.y);
        s0.z = fmaf(cb.x, xb.z, s0.z); s0.w = fmaf(cb.x, xb.w, s0.w);
        s1.x = fmaf(cb.y, xb.x, s1.x); s1.y = fmaf(cb.y, xb.y, s1.y);
        s1.z = fmaf(cb.y, xb.z, s1.z); s1.w = fmaf(cb.y, xb.w, s1.w);
        s2.x = fmaf(cb.z, xb.x, s2.x); s2.y = fmaf(cb.z, xb.y, s2.y);
        s2.z = fmaf(cb.z, xb.z, s2.z); s2.w = fmaf(cb.z, xb.w, s2.w);
        s3.x = fmaf(cb.w, xb.x, s3.x); s3.y = fmaf(cb.w, xb.y, s3.y);
        s3.z = fmaf(cb.w, xb.z, s3.z); s3.w = fmaf(cb.w, xb.w, s3.w);
    }
    if (p < end) {
        float4 c = cf[p];
        int sn = sidx[p];
        float4 xv = X4[(size_t)sn * 32 + lane];
        s0.x = fmaf(c.x, xv.x, s0.x); s0.y = fmaf(c.x, xv.y, s0.y);
        s0.z = fmaf(c.x, xv.z, s0.z); s0.w = fmaf(c.x, xv.w, s0.w);
        s1.x = fmaf(c.y, xv.x, s1.x); s1.y = fmaf(c.y, xv.y, s1.y);
        s1.z = fmaf(c.y, xv.z, s1.z); s1.w = fmaf(c.y, xv.w, s1.w);
        s2.x = fmaf(c.z, xv.x, s2.x); s2.y = fmaf(c.z, xv.y, s2.y);
        s2.z = fmaf(c.z, xv.z, s2.z); s2.w = fmaf(c.z, xv.w, s2.w);
        s3.x = fmaf(c.w, xv.x, s3.x); s3.y = fmaf(c.w, xv.y, s3.y);
        s3.z = fmaf(c.w, xv.z, s3.z); s3.w = fmaf(c.w, xv.w, s3.w);
    }
}

__device__ __forceinline__ void agg_store(int node, int lane, float d,
                                          float4 s0, float4 s1, float4 s2, float4 s3,
                                          __nv_bfloat16* Ahi, __nv_bfloat16* Alo) {
    s0.x *= d; s0.y *= d; s0.z *= d; s0.w *= d;
    s1.x *= d; s1.y *= d; s1.z *= d; s1.w *= d;
    s2.x *= d; s2.y *= d; s2.z *= d; s2.w *= d;
    s3.x *= d; s3.y *= d; s3.z *= d; s3.w *= d;
    size_t base = (size_t)node * KTOT + 4 * lane;
    *(uint2*)(Ahi + base)       = make_uint2(pack_hi(s0.x, s0.y), pack_hi(s0.z, s0.w));
    *(uint2*)(Alo + base)       = make_uint2(pack_lo(s0.x, s0.y), pack_lo(s0.z, s0.w));
    *(uint2*)(Ahi + base + 128) = make_uint2(pack_hi(s1.x, s1.y), pack_hi(s1.z, s1.w));
    *(uint2*)(Alo + base + 128) = make_uint2(pack_lo(s1.x, s1.y), pack_lo(s1.z, s1.w));
    *(uint2*)(Ahi + base + 256) = make_uint2(pack_hi(s2.x, s2.y), pack_hi(s2.z, s2.w));
    *(uint2*)(Alo + base + 256) = make_uint2(pack_lo(s2.x, s2.y), pack_lo(s2.z, s2.w));
    *(uint2*)(Ahi + base + 384) = make_uint2(pack_hi(s3.x, s3.y), pack_hi(s3.z, s3.w));
    *(uint2*)(Alo + base + 384) = make_uint2(pack_lo(s3.x, s3.y), pack_lo(s3.z, s3.w));
}

// ---------------- 5: layer-1 aggregation (gathers entity_table directly, writes A1 S+root) ----------------
__global__ void k_agg0(const float4* __restrict__ tbl, const int* __restrict__ entity) {
    int gw = (blockIdx.x * blockDim.x + threadIdx.x) >> 5;
    int lane = threadIdx.x & 31;
    if (gw >= N_NODES) return;
    float4 s0 = make_float4(0.f, 0.f, 0.f, 0.f);
    float4 s1 = s0, s2 = s0, s3 = s0;
    agg_node(gw, lane, tbl, g_csr_esrc, g_coeff1, s0, s1, s2, s3);
    agg_store(gw, lane, g_invdeg[gw], s0, s1, s2, s3, g_A1hi, g_A1lo);
    // root columns: x[node] = tbl[entity[node]]
    float4 xs = tbl[(size_t)entity[gw] * 32 + lane];
    size_t a = (size_t)gw * KTOT + 512 + 4 * lane;
    *(uint2*)(g_A1hi + a) = make_uint2(pack_hi(xs.x, xs.y), pack_hi(xs.z, xs.w));
    *(uint2*)(g_A1lo + a) = make_uint2(pack_lo(xs.x, xs.y), pack_lo(xs.z, xs.w));
}

// ---------------- 7: layer-2 aggregation (+ relation_emb copy in tail blocks) ----------------
__global__ void k_agg1(const float* __restrict__ rel, float* __restrict__ out) {
    if (blockIdx.x >= AGG_BLOCKS) {
        int i = (blockIdx.x - AGG_BLOCKS) * 256 + threadIdx.x;
        for (; i < 500 * 128; i += 32 * 256)
            out[(size_t)N_NODES * 128 + i] = rel[i];
        return;
    }
    int gw = (blockIdx.x * blockDim.x + threadIdx.x) >> 5;
    int lane = threadIdx.x & 31;
    if (gw >= N_NODES) return;
    float4 s0 = make_float4(0.f, 0.f, 0.f, 0.f);
    float4 s1 = s0, s2 = s0, s3 = s0;
    agg_node(gw, lane, (const float4*)g_h1, g_csr_src, g_coeff2, s0, s1, s2, s3);
    agg_store(gw, lane, g_invdeg[gw], s0, s1, s2, s3, g_A2hi, g_A2lo);
    // A2 root columns are written by the layer-1 GEMM epilogue.
}

// ---------------- 6/8: HMMA GEMM, cp.async double-buffered (R4-proven) ----------------
#define TILE_B 10240
#define BUF_B  (4 * TILE_B)
#define SMEM_GEMM (2 * BUF_B)   // 81920

__global__ __launch_bounds__(256) void k_gemm_mma(
    int layer, const float* __restrict__ bias, float* __restrict__ out_param, int do_relu)
{
    extern __shared__ char smem[];
    uint32_t sbase = smem_u32(smem);
    const __nv_bfloat16* Ahi = (layer == 0) ? g_A1hi : g_A2hi;
    const __nv_bfloat16* Alo = (layer == 0) ? g_A1lo : g_A2lo;
    const __nv_bfloat16* Whi = (layer == 0) ? g_Whi : g_W2hi;
    const __nv_bfloat16* Wlo = (layer == 0) ? g_Wlo : g_W2lo;
    float* out = (layer == 0) ? g_h1 : out_param;

    int tid = threadIdx.x;
    int wid = tid >> 5;
    int lane = tid & 31;
    int bm = blockIdx.x * 128;
    int wm0 = (wid >> 2) * 64;
    int wn0 = (wid & 3) * 32;

    float acc[4][4][4];
    #pragma unroll
    for (int i = 0; i < 4; i++)
        #pragma unroll
        for (int j = 0; j < 4; j++)
            #pragma unroll
            for (int q = 0; q < 4; q++) acc[i][j][q] = 0.f;

    int lr = tid >> 1;
    int lc0 = (tid & 1) * 2;
    int gmr = bm + lr; if (gmr >= N_NODES) gmr = 0;
    uint32_t a_off = (uint32_t)(lane & 15) * 80 + (uint32_t)(lane >> 4) * 16;
    int bg = lane >> 3;
    uint32_t b_off = (uint32_t)((bg >> 1) * 8 + (lane & 7)) * 80 + (uint32_t)(bg & 1) * 16;

    auto load_chunk = [&](int ch, int buf) {
        int kc = ch * 32;
        uint32_t bo = sbase + buf * BUF_B;
        uint32_t drow = (uint32_t)lr * 80;
        #pragma unroll
        for (int c = 0; c < 2; c++) {
            int cc = lc0 + c;
            uint32_t dof = drow + cc * 16;
            int eof = kc + cc * 8;
            cp16(bo + dof,              Ahi + (size_t)gmr * KTOT + eof);
            cp16(bo + TILE_B + dof,     Alo + (size_t)gmr * KTOT + eof);
            cp16(bo + 2 * TILE_B + dof, Whi + lr * KTOT + eof);
            cp16(bo + 3 * TILE_B + dof, Wlo + lr * KTOT + eof);
        }
    };

    load_chunk(0, 0);
    CP_COMMIT();

    #pragma unroll 1
    for (int ch = 0; ch < 20; ch++) {
        int buf = ch & 1;
        if (ch < 19) {
            load_chunk(ch + 1, buf ^ 1);
            CP_COMMIT();
            CP_WAIT(1);
        } else {
            CP_WAIT(0);
        }
        __syncthreads();

        uint32_t a_hi_base = sbase + buf * BUF_B;
        uint32_t a_lo_base = a_hi_base + TILE_B;
        uint32_t b_hi_base = a_hi_base + 2 * TILE_B;
        uint32_t b_lo_base = a_hi_base + 3 * TILE_B;

        #pragma unroll
        for (int kk = 0; kk < 2; kk++) {
            uint32_t kb = (uint32_t)kk * 32;
            uint32_t ahi[4][4], alo[4][4];
            #pragma unroll
            for (int mf = 0; mf < 4; mf++) {
                uint32_t o = (uint32_t)(wm0 + mf * 16) * 80 + a_off + kb;
                ldm_x4(ahi[mf], a_hi_base + o);
                ldm_x4(alo[mf], a_lo_base + o);
            }
            uint32_t bhi[4][2], blo[4][2];
            #pragma unroll
            for (int pr = 0; pr < 2; pr++) {
                uint32_t o = (uint32_t)(wn0 + pr * 16) * 80 + b_off + kb;
                uint32_t th[4], tl[4];
                ldm_x4(th, b_hi_base + o);
                ldm_x4(tl, b_lo_base + o);
                bhi[pr * 2][0] = th[0]; bhi[pr * 2][1] = th[1];
                bhi[pr * 2 + 1][0] = th[2]; bhi[pr * 2 + 1][1] = th[3];
                blo[pr * 2][0] = tl[0]; blo[pr * 2][1] = tl[1];
                blo[pr * 2 + 1][0] = tl[2]; blo[pr * 2 + 1][1] = tl[3];
            }
            #pragma unroll
            for (int mf = 0; mf < 4; mf++)
                #pragma unroll
                for (int nf = 0; nf < 4; nf++) {
                    mma16816(acc[mf][nf], ahi[mf], bhi[nf]);
                    mma16816(acc[mf][nf], ahi[mf], blo[nf]);
                    mma16816(acc[mf][nf], alo[mf], bhi[nf]);
                }
        }
        __syncthreads();
    }

    int qm = lane >> 2;
    int qn = (lane & 3) * 2;
    #pragma unroll
    for (int nf = 0; nf < 4; nf++) {
        int n = wn0 + nf * 8 + qn;
        float b0 = bias[n], b1 = bias[n + 1];
        #pragma unroll
        for (int mf = 0; mf < 4; mf++) {
            int m0 = bm + wm0 + mf * 16 + qm;
            float2 lo = make_float2(acc[mf][nf][0] + b0, acc[mf][nf][1] + b1);
            float2 hi = make_float2(acc[mf][nf][2] + b0, acc[mf][nf][3] + b1);
            if (do_relu) {
                lo.x = fmaxf(lo.x, 0.f); lo.y = fmaxf(lo.y, 0.f);
                hi.x = fmaxf(hi.x, 0.f); hi.y = fmaxf(hi.y, 0.f);
            }
            if (m0 < N_NODES) {
                *(float2*)(out + (size_t)m0 * 128 + n) = lo;
                if (layer == 0) {
                    size_t a = (size_t)m0 * KTOT + 512 + n;
                    *(uint32_t*)(g_A2hi + a) = pack_hi(lo.x, lo.y);
                    *(uint32_t*)(g_A2lo + a) = pack_lo(lo.x, lo.y);
                }
            }
            if (m0 + 8 < N_NODES) {
                *(float2*)(out + (size_t)(m0 + 8) * 128 + n) = hi;
                if (layer == 0) {
                    size_t a = (size_t)(m0 + 8) * KTOT + 512 + n;
                    *(uint32_t*)(g_A2hi + a) = pack_hi(hi.x, hi.y);
                    *(uint32_t*)(g_A2lo + a) = pack_lo(hi.x, hi.y);
                }
            }
        }
    }
}

// ---------------- launch ----------------
extern "C" void kernel_launch(void* const* d_in, const int* in_sizes, int n_in,
                              void* d_out, int out_size) {
    const int*   entity       = (const int*)d_in[0];
    const int*   edge_index   = (const int*)d_in[1];
    const int*   edge_type    = (const int*)d_in[2];
    const float* edge_norm    = (const float*)d_in[3];
    // d_in[4] = DAD_rel (unused by reference output)
    const float* entity_table = (const float*)d_in[5];
    const float* relation_emb = (const float*)d_in[6];
    const float* basis1 = (const float*)d_in[7];
    const float* att1   = (const float*)d_in[8];
    const float* root1  = (const float*)d_in[9];
    const float* bias1  = (const float*)d_in[10];
    const float* basis2 = (const float*)d_in[11];
    const float* att2   = (const float*)d_in[12];
    const float* root2  = (const float*)d_in[13];
    const float* bias2  = (const float*)d_in[14];

    const int* src = edge_index;
    const int* dst = edge_index + N_EDGES;
    float* out = (float*)d_out;

    static int smem_set = 0;
    if (!smem_set) {
        cudaFuncSetAttribute(k_gemm_mma, cudaFuncAttributeMaxDynamicSharedMemorySize, SMEM_GEMM);
        smem_set = 1;
    }

    int gemm_blocks = (N_NODES + 127) / 128;   // 782

    // 1: zero deg + scan state
    k_zero<<<(N_NODES + 255) / 256, 256>>>();
    // 2: histogram + weight split (both layers)
    k_hist_prepw2<<<(N_EDGES + 255) / 256, 256>>>(dst, basis1, root1, basis2, root2);
    // 3: single-pass decoupled-lookback scan -> rowptr/cursor/invdeg
    k_scan<<<SCAN_BLOCKS, 1024>>>();
    // 4: scatter (CSR src + entity src + both layers' coefficients)
    k_scatter<<<(N_EDGES + 255) / 256, 256>>>(dst, src, entity, edge_type, edge_norm,
                                              (const float4*)att1, (const float4*)att2);
    // 5: layer-1 aggregation (direct entity_table gathers; writes A1 incl. root)
    k_agg0<<<AGG_BLOCKS, 256>>>((const float4*)entity_table, entity);
    // 6: layer-1 GEMM (relu) -> h1 + A2 root cols          [ncu captures this]
    k_gemm_mma<<<gemm_blocks, 256, SMEM_GEMM>>>(0, bias1, nullptr, 1);
    // 7: layer-2 aggregation + relation_emb copy
    k_agg1<<<AGG_BLOCKS + 32, 256>>>(relation_emb, out);
    // 8: layer-2 GEMM (no relu) -> d_out
    k_gemm_mma<<<gemm_blocks, 256, SMEM_GEMM>>>(1, bias2, out, 0);
}